// round 1
// baseline (speedup 1.0000x reference)
#include <cuda_runtime.h>
#include <math.h>

// ---------------- model constants ----------------
#define BB    32
#define NPAT  196
#define NT    197
#define DIMV  768
#define H3    2304
#define HID   3072
#define NH    12
#define HD    64
#define NC    1000
#define MTOK  (BB*NT)     // 6304
#define MPAT  (BB*NPAT)   // 6272
#define NN    (NT*NT)     // 38809
#define SCALE_QK 0.125f
#define LNEPS 1e-6f

// ---------------- scratch (device globals; no allocation allowed) ----------------
__device__ float g_p   [(size_t)MPAT*DIMV];   // gathered patches
__device__ float g_pe  [(size_t)MPAT*DIMV];   // patch-embed GEMM out
__device__ float g_h   [(size_t)MTOK*DIMV];   // residual stream
__device__ float g_a   [(size_t)MTOK*DIMV];   // LN output
__device__ float g_qkv [(size_t)MTOK*H3];
__device__ float g_attn[(size_t)BB*NH*NN];
__device__ float g_attn2[(size_t)BB*NH*NN];
__device__ float g_o   [(size_t)MTOK*DIMV];   // attention output
__device__ float g_ffn [(size_t)MTOK*HID];
__device__ float g_cls [(size_t)BB*DIMV];

// ---------------- patch gather ----------------
__global__ void build_patches_kernel(const float* __restrict__ x, float* __restrict__ p)
{
    long idx = (long)blockIdx.x * 256 + threadIdx.x;
    if (idx >= (long)MPAT * DIMV) return;
    int c  = (int)(idx % DIMV);
    long t = idx / DIMV;
    int np = (int)(t % NPAT);
    int b  = (int)(t / NPAT);
    int ch = c >> 8, rem = c & 255, py = rem >> 4, px = rem & 15;
    int gy = np / 14, gx = np % 14;
    p[idx] = x[(((long)b * 3 + ch) * 224 + gy * 16 + py) * 224 + gx * 16 + px];
}

// ---------------- assemble h = concat(cls, patch_out) + pos ----------------
__global__ void assemble_kernel(const float* __restrict__ pe, const float* __restrict__ cls_t,
                                const float* __restrict__ pos, float* __restrict__ h)
{
    long idx = (long)blockIdx.x * 256 + threadIdx.x;
    if (idx >= (long)MTOK * DIMV) return;
    int c  = (int)(idx % DIMV);
    long t = idx / DIMV;
    int n  = (int)(t % NT);
    int b  = (int)(t / NT);
    float v = (n == 0) ? cls_t[c] : pe[((long)b * NPAT + (n - 1)) * DIMV + c];
    h[idx] = v + pos[(long)n * DIMV + c];
}

// ---------------- layernorm (one block per row, 768 elems) ----------------
__global__ void ln_kernel(const float* __restrict__ x, long xstride,
                          const float* __restrict__ w, const float* __restrict__ b,
                          float* __restrict__ out)
{
    int row = blockIdx.x;
    const float* xr = x + (long)row * xstride;
    int t = threadIdx.x;
    float v0 = xr[t], v1 = xr[t + 256], v2 = xr[t + 512];
    float s1 = v0 + v1 + v2;
    float s2 = v0 * v0 + v1 * v1 + v2 * v2;
    #pragma unroll
    for (int off = 16; off; off >>= 1) {
        s1 += __shfl_xor_sync(0xffffffffu, s1, off);
        s2 += __shfl_xor_sync(0xffffffffu, s2, off);
    }
    __shared__ float r1[8], r2[8];
    if ((t & 31) == 0) { r1[t >> 5] = s1; r2[t >> 5] = s2; }
    __syncthreads();
    float tot1 = 0.f, tot2 = 0.f;
    #pragma unroll
    for (int i = 0; i < 8; i++) { tot1 += r1[i]; tot2 += r2[i]; }
    float mean = tot1 * (1.0f / 768.0f);
    float var  = tot2 * (1.0f / 768.0f) - mean * mean;
    float rstd = rsqrtf(var + LNEPS);
    float* orow = out + (long)row * DIMV;
    orow[t]       = (v0 - mean) * rstd * w[t]       + b[t];
    orow[t + 256] = (v1 - mean) * rstd * w[t + 256] + b[t + 256];
    orow[t + 512] = (v2 - mean) * rstd * w[t + 512] + b[t + 512];
}

// ---------------- generic GEMM: C = A[M,K] @ W[K,Nd] + bias (+gelu / +residual) ----------------
// 64x64 tile, BK=16, 256 threads, 4x4 microtile.
template<int ACT, int RES>
__global__ void gemm_kernel(const float* __restrict__ A, const float* __restrict__ W,
                            const float* __restrict__ bias, const float* __restrict__ R,
                            float* __restrict__ C, int M, int K, int Nd)
{
    __shared__ float As[16][64];
    __shared__ float Bs[16][64];
    int tid = threadIdx.x;
    int tx = tid & 15, ty = tid >> 4;
    int m0 = blockIdx.y * 64;
    int n0 = blockIdx.x * 64;
    float acc[4][4] = {};
    int arow = tid >> 2;           // 0..63
    int ak   = (tid & 3) * 4;      // 0,4,8,12
    int bk   = tid >> 4;           // 0..15
    int bcol = (tid & 15) * 4;     // 0..60

    for (int k0 = 0; k0 < K; k0 += 16) {
        float4 av = make_float4(0.f, 0.f, 0.f, 0.f);
        if (m0 + arow < M)
            av = *(const float4*)(A + (long)(m0 + arow) * K + k0 + ak);
        As[ak + 0][arow] = av.x; As[ak + 1][arow] = av.y;
        As[ak + 2][arow] = av.z; As[ak + 3][arow] = av.w;

        float4 bv;
        if (n0 + bcol + 3 < Nd) {
            bv = *(const float4*)(W + (long)(k0 + bk) * Nd + n0 + bcol);
        } else {
            const float* wp = W + (long)(k0 + bk) * Nd + n0 + bcol;
            float tmp[4] = {0.f, 0.f, 0.f, 0.f};
            #pragma unroll
            for (int j = 0; j < 4; j++) if (n0 + bcol + j < Nd) tmp[j] = wp[j];
            bv = make_float4(tmp[0], tmp[1], tmp[2], tmp[3]);
        }
        *(float4*)&Bs[bk][bcol] = bv;
        __syncthreads();

        #pragma unroll
        for (int kk = 0; kk < 16; kk++) {
            float4 a = *(const float4*)&As[kk][ty * 4];
            float4 b = *(const float4*)&Bs[kk][tx * 4];
            float ar[4] = {a.x, a.y, a.z, a.w};
            float br[4] = {b.x, b.y, b.z, b.w};
            #pragma unroll
            for (int i = 0; i < 4; i++)
                #pragma unroll
                for (int j = 0; j < 4; j++)
                    acc[i][j] += ar[i] * br[j];
        }
        __syncthreads();
    }

    #pragma unroll
    for (int i = 0; i < 4; i++) {
        int row = m0 + ty * 4 + i;
        if (row >= M) continue;
        #pragma unroll
        for (int j = 0; j < 4; j++) {
            int col = n0 + tx * 4 + j;
            if (col >= Nd) continue;
            float v = acc[i][j] + bias[col];
            if (ACT == 1) v = 0.5f * v * (1.0f + erff(v * 0.70710678118654752f));
            long idx = (long)row * Nd + col;
            if (RES) v += R[idx];
            C[idx] = v;
        }
    }
}

// ---------------- attention scores: attn[bh,n,m] = SCALE * q.k ----------------
__global__ void scores_kernel(const float* __restrict__ qkv, float* __restrict__ attn)
{
    __shared__ float Qs[32][65];
    __shared__ float Ks[32][65];
    int bh = blockIdx.z;
    int b = bh / NH, hh = bh % NH;
    int n0 = blockIdx.y * 32, m0 = blockIdx.x * 32;
    int t = threadIdx.x;
    #pragma unroll
    for (int i = 0; i < 2; i++) {
        int f = t + i * 256;         // 0..511
        int row = f >> 4;            // 0..31
        int d4 = (f & 15) * 4;
        int nq = n0 + row;
        float4 qv = make_float4(0.f, 0.f, 0.f, 0.f);
        if (nq < NT)
            qv = *(const float4*)(qkv + ((long)(b * NT + nq) * 3 + 0) * DIMV + hh * HD + d4);
        Qs[row][d4] = qv.x; Qs[row][d4 + 1] = qv.y; Qs[row][d4 + 2] = qv.z; Qs[row][d4 + 3] = qv.w;
        int nk = m0 + row;
        float4 kv = make_float4(0.f, 0.f, 0.f, 0.f);
        if (nk < NT)
            kv = *(const float4*)(qkv + ((long)(b * NT + nk) * 3 + 1) * DIMV + hh * HD + d4);
        Ks[row][d4] = kv.x; Ks[row][d4 + 1] = kv.y; Ks[row][d4 + 2] = kv.z; Ks[row][d4 + 3] = kv.w;
    }
    __syncthreads();
    int tx = t & 31, ty = t >> 5;      // ty 0..7
    float acc[4] = {0.f, 0.f, 0.f, 0.f};
    #pragma unroll 8
    for (int d = 0; d < 64; d++) {
        float kv = Ks[tx][d];
        #pragma unroll
        for (int r = 0; r < 4; r++) acc[r] += Qs[ty * 4 + r][d] * kv;
    }
    #pragma unroll
    for (int r = 0; r < 4; r++) {
        int n = n0 + ty * 4 + r, m = m0 + tx;
        if (n < NT && m < NT)
            attn[(long)bh * NN + (long)n * NT + m] = acc[r] * SCALE_QK;
    }
}

// ---------------- head mixing: out[b,g,:,:] = sum_h in[b,h,:,:] * w[h,g] ----------------
__global__ void headmix_kernel(const float* __restrict__ in, const float* __restrict__ w,
                               float* __restrict__ out)
{
    __shared__ float ws[NH * NH];
    int t = threadIdx.x;
    if (t < NH * NH) ws[t] = w[t];
    __syncthreads();
    long pos = (long)blockIdx.x * 256 + t;
    if (pos >= (long)BB * NN) return;
    int b  = (int)(pos / NN);
    int nm = (int)(pos % NN);
    float vin[NH];
    #pragma unroll
    for (int h2 = 0; h2 < NH; h2++) vin[h2] = in[((long)(b * NH + h2)) * NN + nm];
    #pragma unroll
    for (int g = 0; g < NH; g++) {
        float s = 0.f;
        #pragma unroll
        for (int h2 = 0; h2 < NH; h2++) s += vin[h2] * ws[h2 * NH + g];
        out[((long)(b * NH + g)) * NN + nm] = s;
    }
}

// ---------------- softmax over last dim (warp per row of 197) ----------------
__global__ void softmax_kernel(float* __restrict__ a)
{
    int r = blockIdx.x * 8 + (threadIdx.x >> 5);
    if (r >= BB * NH * NT) return;
    int lane = threadIdx.x & 31;
    float* p = a + (long)r * NT;
    float v[7];
    float mx = -1e30f;
    #pragma unroll
    for (int i = 0; i < 7; i++) {
        int m = lane + i * 32;
        v[i] = (m < NT) ? p[m] : -1e30f;
        mx = fmaxf(mx, v[i]);
    }
    #pragma unroll
    for (int off = 16; off; off >>= 1) mx = fmaxf(mx, __shfl_xor_sync(0xffffffffu, mx, off));
    float s = 0.f;
    #pragma unroll
    for (int i = 0; i < 7; i++) { v[i] = __expf(v[i] - mx); s += v[i]; }
    #pragma unroll
    for (int off = 16; off; off >>= 1) s += __shfl_xor_sync(0xffffffffu, s, off);
    float inv = 1.0f / s;
    #pragma unroll
    for (int i = 0; i < 7; i++) {
        int m = lane + i * 32;
        if (m < NT) p[m] = v[i] * inv;
    }
}

// ---------------- AV: o[b,n,h*64+d] = sum_m attn[bh,n,m] * v[b,h,m,d] ----------------
__global__ void av_kernel(const float* __restrict__ attn, const float* __restrict__ qkv,
                          float* __restrict__ o)
{
    __shared__ float As[32][33];
    __shared__ float Vs[32][65];
    int bh = blockIdx.y;
    int b = bh / NH, hh = bh % NH;
    int n0 = blockIdx.x * 32;
    int t = threadIdx.x;
    int d = t & 63, ng = t >> 6;      // ng 0..3
    float acc[8] = {};
    for (int m0 = 0; m0 < NT; m0 += 32) {
        {
            int row = t >> 3;          // 0..31
            int c4 = (t & 7) * 4;
            int n = n0 + row;
            #pragma unroll
            for (int j = 0; j < 4; j++) {
                int m = m0 + c4 + j;
                As[row][c4 + j] = (n < NT && m < NT)
                    ? attn[(long)bh * NN + (long)n * NT + m] : 0.f;
            }
        }
        #pragma unroll
        for (int i = 0; i < 2; i++) {
            int f = t + i * 256;
            int row = f >> 4;
            int d4 = (f & 15) * 4;
            int m = m0 + row;
            float4 vv = make_float4(0.f, 0.f, 0.f, 0.f);
            if (m < NT)
                vv = *(const float4*)(qkv + ((long)(b * NT + m) * 3 + 2) * DIMV + hh * HD + d4);
            Vs[row][d4] = vv.x; Vs[row][d4 + 1] = vv.y; Vs[row][d4 + 2] = vv.z; Vs[row][d4 + 3] = vv.w;
        }
        __syncthreads();
        #pragma unroll
        for (int mm = 0; mm < 32; mm++) {
            float vv = Vs[mm][d];
            #pragma unroll
            for (int rr = 0; rr < 8; rr++) acc[rr] += As[ng * 8 + rr][mm] * vv;
        }
        __syncthreads();
    }
    #pragma unroll
    for (int rr = 0; rr < 8; rr++) {
        int n = n0 + ng * 8 + rr;
        if (n < NT) o[(long)(b * NT + n) * DIMV + hh * HD + d] = acc[rr];
    }
}

// ---------------- host launcher ----------------
extern "C" void kernel_launch(void* const* d_in, const int* in_sizes, int n_in,
                              void* d_out, int out_size)
{
    const float* x          = (const float*)d_in[0];
    const float* patch_w    = (const float*)d_in[1];
    const float* patch_b    = (const float*)d_in[2];
    const float* cls_token  = (const float*)d_in[3];
    const float* pos_embed  = (const float*)d_in[4];
    const float* ln1_w      = (const float*)d_in[5];
    const float* ln1_b      = (const float*)d_in[6];
    const float* qkv_w      = (const float*)d_in[7];
    const float* qkv_b      = (const float*)d_in[8];
    const float* pre_w      = (const float*)d_in[9];
    const float* post_w     = (const float*)d_in[10];
    const float* attnproj_w = (const float*)d_in[11];
    const float* attnproj_b = (const float*)d_in[12];
    const float* ln2_w      = (const float*)d_in[13];
    const float* ln2_b      = (const float*)d_in[14];
    const float* fc1_w      = (const float*)d_in[15];
    const float* fc1_b      = (const float*)d_in[16];
    const float* fc2_w      = (const float*)d_in[17];
    const float* fc2_b      = (const float*)d_in[18];
    const float* norm_w     = (const float*)d_in[19];
    const float* norm_b     = (const float*)d_in[20];
    const float* head_w     = (const float*)d_in[21];
    const float* head_b     = (const float*)d_in[22];

    float *p, *pe, *h, *a, *qkv, *attn, *attn2, *o, *ffn, *cls;
    cudaGetSymbolAddress((void**)&p,     g_p);
    cudaGetSymbolAddress((void**)&pe,    g_pe);
    cudaGetSymbolAddress((void**)&h,     g_h);
    cudaGetSymbolAddress((void**)&a,     g_a);
    cudaGetSymbolAddress((void**)&qkv,   g_qkv);
    cudaGetSymbolAddress((void**)&attn,  g_attn);
    cudaGetSymbolAddress((void**)&attn2, g_attn2);
    cudaGetSymbolAddress((void**)&o,     g_o);
    cudaGetSymbolAddress((void**)&ffn,   g_ffn);
    cudaGetSymbolAddress((void**)&cls,   g_cls);

    // patch embedding
    {
        long tot = (long)MPAT * DIMV;
        build_patches_kernel<<<(unsigned)((tot + 255) / 256), 256>>>(x, p);
        gemm_kernel<0, 0><<<dim3(12, 98), 256>>>(p, patch_w, patch_b, nullptr, pe, MPAT, DIMV, DIMV);
        long tot2 = (long)MTOK * DIMV;
        assemble_kernel<<<(unsigned)((tot2 + 255) / 256), 256>>>(pe, cls_token, pos_embed, h);
    }

    unsigned mixgrid = (unsigned)(((long)BB * NN + 255) / 256);
    unsigned smgrid  = (unsigned)((BB * NH * NT + 7) / 8);

    for (int i = 0; i < 12; i++) {
        ln_kernel<<<MTOK, 256>>>(h, DIMV, ln1_w + i * DIMV, ln1_b + i * DIMV, a);
        gemm_kernel<0, 0><<<dim3(36, 99), 256>>>(a, qkv_w + (long)i * DIMV * H3,
                                                 qkv_b + i * H3, nullptr, qkv, MTOK, DIMV, H3);
        scores_kernel<<<dim3(7, 7, BB * NH), 256>>>(qkv, attn);
        headmix_kernel<<<mixgrid, 256>>>(attn, pre_w + i * NH * NH, attn2);
        softmax_kernel<<<smgrid, 256>>>(attn2);
        headmix_kernel<<<mixgrid, 256>>>(attn2, post_w + i * NH * NH, attn);
        av_kernel<<<dim3(7, BB * NH), 256>>>(attn, qkv, o);
        gemm_kernel<0, 1><<<dim3(12, 99), 256>>>(o, attnproj_w + (long)i * DIMV * DIMV,
                                                 attnproj_b + i * DIMV, h, h, MTOK, DIMV, DIMV);
        ln_kernel<<<MTOK, 256>>>(h, DIMV, ln2_w + i * DIMV, ln2_b + i * DIMV, a);
        gemm_kernel<1, 0><<<dim3(48, 99), 256>>>(a, fc1_w + (long)i * DIMV * HID,
                                                 fc1_b + i * HID, nullptr, ffn, MTOK, DIMV, HID);
        gemm_kernel<0, 1><<<dim3(12, 99), 256>>>(ffn, fc2_w + (long)i * HID * DIMV,
                                                 fc2_b + i * DIMV, h, h, MTOK, HID, DIMV);
    }

    // final LN on cls rows only, then classifier head
    ln_kernel<<<BB, 256>>>(h, (long)NT * DIMV, norm_w, norm_b, cls);
    gemm_kernel<0, 0><<<dim3(16, 1), 256>>>(cls, head_w, head_b, nullptr,
                                            (float*)d_out, BB, DIMV, NC);
}

// round 5
// speedup vs baseline: 1.9643x; 1.9643x over previous
#include <cuda_runtime.h>
#include <math.h>
#include <stdint.h>

// ---------------- model constants ----------------
#define BB    32
#define NPAT  196
#define NT    197
#define DIMV  768
#define H3    2304
#define HID   3072
#define NH    12
#define HD    64
#define NC    1000
#define MTOK  (BB*NT)     // 6304
#define MPAT  (BB*NPAT)   // 6272
#define NN    (NT*NT)     // 38809
#define SCALE_QK 0.125f
#define LNEPS 1e-6f

// ---------------- scratch (device globals; no allocation allowed) ----------------
__device__ float g_p   [(size_t)MPAT*DIMV];
__device__ float g_pe  [(size_t)MPAT*DIMV];
__device__ float g_h   [(size_t)MTOK*DIMV];
__device__ float g_a   [(size_t)MTOK*DIMV];
__device__ float g_qkv [(size_t)MTOK*H3];
__device__ float g_attn[(size_t)BB*NH*NN];
__device__ float g_attn2[(size_t)BB*NH*NN];
__device__ float g_o   [(size_t)MTOK*DIMV];
__device__ float g_ffn [(size_t)MTOK*HID];
__device__ float g_cls [(size_t)BB*DIMV];

// cvt.rna.tf32.f32 requires a .b32 destination register ("=r", NOT "=f").
__device__ __forceinline__ float to_tf32(float x) {
    uint32_t r;
    asm("cvt.rna.tf32.f32 %0, %1;" : "=r"(r) : "f"(x));
    return __uint_as_float(r);
}

// ---------------- patch gather ----------------
__global__ void build_patches_kernel(const float* __restrict__ x, float* __restrict__ p)
{
    long idx = (long)blockIdx.x * 256 + threadIdx.x;
    if (idx >= (long)MPAT * DIMV) return;
    int c  = (int)(idx % DIMV);
    long t = idx / DIMV;
    int np = (int)(t % NPAT);
    int b  = (int)(t / NPAT);
    int ch = c >> 8, rem = c & 255, py = rem >> 4, px = rem & 15;
    int gy = np / 14, gx = np % 14;
    p[idx] = x[(((long)b * 3 + ch) * 224 + gy * 16 + py) * 224 + gx * 16 + px];
}

// ---------------- assemble h = concat(cls, patch_out) + pos ----------------
__global__ void assemble_kernel(const float* __restrict__ pe, const float* __restrict__ cls_t,
                                const float* __restrict__ pos, float* __restrict__ h)
{
    long idx = (long)blockIdx.x * 256 + threadIdx.x;
    if (idx >= (long)MTOK * DIMV) return;
    int c  = (int)(idx % DIMV);
    long t = idx / DIMV;
    int n  = (int)(t % NT);
    int b  = (int)(t / NT);
    float v = (n == 0) ? cls_t[c] : pe[((long)b * NPAT + (n - 1)) * DIMV + c];
    h[idx] = v + pos[(long)n * DIMV + c];
}

// ---------------- layernorm ----------------
__global__ void ln_kernel(const float* __restrict__ x, long xstride,
                          const float* __restrict__ w, const float* __restrict__ b,
                          float* __restrict__ out)
{
    int row = blockIdx.x;
    const float* xr = x + (long)row * xstride;
    int t = threadIdx.x;
    float v0 = xr[t], v1 = xr[t + 256], v2 = xr[t + 512];
    float s1 = v0 + v1 + v2;
    float s2 = v0 * v0 + v1 * v1 + v2 * v2;
    #pragma unroll
    for (int off = 16; off; off >>= 1) {
        s1 += __shfl_xor_sync(0xffffffffu, s1, off);
        s2 += __shfl_xor_sync(0xffffffffu, s2, off);
    }
    __shared__ float r1[8], r2[8];
    if ((t & 31) == 0) { r1[t >> 5] = s1; r2[t >> 5] = s2; }
    __syncthreads();
    float tot1 = 0.f, tot2 = 0.f;
    #pragma unroll
    for (int i = 0; i < 8; i++) { tot1 += r1[i]; tot2 += r2[i]; }
    float mean = tot1 * (1.0f / 768.0f);
    float var  = tot2 * (1.0f / 768.0f) - mean * mean;
    float rstd = rsqrtf(var + LNEPS);
    float* orow = out + (long)row * DIMV;
    orow[t]       = (v0 - mean) * rstd * w[t]       + b[t];
    orow[t + 256] = (v1 - mean) * rstd * w[t + 256] + b[t + 256];
    orow[t + 512] = (v2 - mean) * rstd * w[t + 512] + b[t + 512];
}

// ---------------- TF32 tensor-core GEMM ----------------
// C[M,Nd] = A[M,K] @ W[K,Nd] + bias (+gelu / +residual)
// 128x128x32 block tile, 256 threads = 4(M) x 2(N) warps, warp tile 32x64.
template<int ACT, int RES>
__global__ void __launch_bounds__(256) gemm_tc(
    const float* __restrict__ A, const float* __restrict__ W,
    const float* __restrict__ bias, const float* __restrict__ R,
    float* __restrict__ C, int M, int K, int Nd)
{
    __shared__ float As[128][36];
    __shared__ float Bs[32][136];

    int tid  = threadIdx.x;
    int warp = tid >> 5, lane = tid & 31;
    int g = lane >> 2, tig = lane & 3;
    int wm = (warp & 3) * 32;
    int wn = (warp >> 2) * 64;
    int m0 = blockIdx.y * 128;
    int n0 = blockIdx.x * 128;

    float c[2][8][4];
    #pragma unroll
    for (int im = 0; im < 2; im++)
        #pragma unroll
        for (int jn = 0; jn < 8; jn++)
            #pragma unroll
            for (int q = 0; q < 4; q++) c[im][jn][q] = 0.f;

    int ar = tid >> 3;
    int ac = (tid & 7) * 4;
    int bk = tid >> 5;
    int bc = (tid & 31) * 4;

    for (int k0 = 0; k0 < K; k0 += 32) {
        #pragma unroll
        for (int i = 0; i < 4; i++) {
            int row = ar + 32 * i;
            float4 v = make_float4(0.f, 0.f, 0.f, 0.f);
            if (m0 + row < M)
                v = *(const float4*)(A + (long)(m0 + row) * K + k0 + ac);
            As[row][ac + 0] = to_tf32(v.x);
            As[row][ac + 1] = to_tf32(v.y);
            As[row][ac + 2] = to_tf32(v.z);
            As[row][ac + 3] = to_tf32(v.w);
        }
        #pragma unroll
        for (int i = 0; i < 4; i++) {
            int kk = bk + 8 * i;
            float4 v = make_float4(0.f, 0.f, 0.f, 0.f);
            if (n0 + bc + 3 < Nd) {
                v = *(const float4*)(W + (long)(k0 + kk) * Nd + n0 + bc);
            } else {
                const float* wp = W + (long)(k0 + kk) * Nd + n0 + bc;
                float tmp[4] = {0.f, 0.f, 0.f, 0.f};
                #pragma unroll
                for (int j = 0; j < 4; j++) if (n0 + bc + j < Nd) tmp[j] = wp[j];
                v = make_float4(tmp[0], tmp[1], tmp[2], tmp[3]);
            }
            Bs[kk][bc + 0] = to_tf32(v.x);
            Bs[kk][bc + 1] = to_tf32(v.y);
            Bs[kk][bc + 2] = to_tf32(v.z);
            Bs[kk][bc + 3] = to_tf32(v.w);
        }
        __syncthreads();

        #pragma unroll
        for (int ks = 0; ks < 4; ks++) {
            uint32_t a[2][4], b[8][2];
            #pragma unroll
            for (int im = 0; im < 2; im++) {
                int r = wm + im * 16 + g;
                int cc = ks * 8 + tig;
                a[im][0] = __float_as_uint(As[r][cc]);
                a[im][1] = __float_as_uint(As[r + 8][cc]);
                a[im][2] = __float_as_uint(As[r][cc + 4]);
                a[im][3] = __float_as_uint(As[r + 8][cc + 4]);
            }
            #pragma unroll
            for (int jn = 0; jn < 8; jn++) {
                int col = wn + jn * 8 + g;
                b[jn][0] = __float_as_uint(Bs[ks * 8 + tig][col]);
                b[jn][1] = __float_as_uint(Bs[ks * 8 + tig + 4][col]);
            }
            #pragma unroll
            for (int im = 0; im < 2; im++)
                #pragma unroll
                for (int jn = 0; jn < 8; jn++) {
                    asm volatile(
                        "mma.sync.aligned.m16n8k8.row.col.f32.tf32.tf32.f32 "
                        "{%0,%1,%2,%3}, {%4,%5,%6,%7}, {%8,%9}, {%0,%1,%2,%3};"
                        : "+f"(c[im][jn][0]), "+f"(c[im][jn][1]),
                          "+f"(c[im][jn][2]), "+f"(c[im][jn][3])
                        : "r"(a[im][0]), "r"(a[im][1]), "r"(a[im][2]), "r"(a[im][3]),
                          "r"(b[jn][0]), "r"(b[jn][1]));
                }
        }
        __syncthreads();
    }

    #pragma unroll
    for (int im = 0; im < 2; im++) {
        int r0 = m0 + wm + im * 16 + g;
        #pragma unroll
        for (int jn = 0; jn < 8; jn++) {
            int col0 = n0 + wn + jn * 8 + tig * 2;
            #pragma unroll
            for (int q = 0; q < 4; q++) {
                int row = r0 + (q >= 2 ? 8 : 0);
                int col = col0 + (q & 1);
                if (row >= M || col >= Nd) continue;
                float v = c[im][jn][q] + bias[col];
                if (ACT == 1) v = 0.5f * v * (1.0f + erff(v * 0.70710678118654752f));
                long idx = (long)row * Nd + col;
                if (RES) v += R[idx];
                C[idx] = v;
            }
        }
    }
}

// ---------------- fallback SIMT GEMM (head only: M=32) ----------------
template<int ACT, int RES>
__global__ void gemm_kernel(const float* __restrict__ A, const float* __restrict__ W,
                            const float* __restrict__ bias, const float* __restrict__ R,
                            float* __restrict__ C, int M, int K, int Nd)
{
    __shared__ float As[16][64];
    __shared__ float Bs[16][64];
    int tid = threadIdx.x;
    int tx = tid & 15, ty = tid >> 4;
    int m0 = blockIdx.y * 64;
    int n0 = blockIdx.x * 64;
    float acc[4][4] = {};
    int arow = tid >> 2;
    int ak   = (tid & 3) * 4;
    int bk   = tid >> 4;
    int bcol = (tid & 15) * 4;

    for (int k0 = 0; k0 < K; k0 += 16) {
        float4 av = make_float4(0.f, 0.f, 0.f, 0.f);
        if (m0 + arow < M)
            av = *(const float4*)(A + (long)(m0 + arow) * K + k0 + ak);
        As[ak + 0][arow] = av.x; As[ak + 1][arow] = av.y;
        As[ak + 2][arow] = av.z; As[ak + 3][arow] = av.w;

        float4 bv;
        if (n0 + bcol + 3 < Nd) {
            bv = *(const float4*)(W + (long)(k0 + bk) * Nd + n0 + bcol);
        } else {
            const float* wp = W + (long)(k0 + bk) * Nd + n0 + bcol;
            float tmp[4] = {0.f, 0.f, 0.f, 0.f};
            #pragma unroll
            for (int j = 0; j < 4; j++) if (n0 + bcol + j < Nd) tmp[j] = wp[j];
            bv = make_float4(tmp[0], tmp[1], tmp[2], tmp[3]);
        }
        *(float4*)&Bs[bk][bcol] = bv;
        __syncthreads();

        #pragma unroll
        for (int kk = 0; kk < 16; kk++) {
            float4 a = *(const float4*)&As[kk][ty * 4];
            float4 b = *(const float4*)&Bs[kk][tx * 4];
            float ar[4] = {a.x, a.y, a.z, a.w};
            float br[4] = {b.x, b.y, b.z, b.w};
            #pragma unroll
            for (int i = 0; i < 4; i++)
                #pragma unroll
                for (int j = 0; j < 4; j++)
                    acc[i][j] += ar[i] * br[j];
        }
        __syncthreads();
    }

    #pragma unroll
    for (int i = 0; i < 4; i++) {
        int row = m0 + ty * 4 + i;
        if (row >= M) continue;
        #pragma unroll
        for (int j = 0; j < 4; j++) {
            int col = n0 + tx * 4 + j;
            if (col >= Nd) continue;
            float v = acc[i][j] + bias[col];
            if (ACT == 1) v = 0.5f * v * (1.0f + erff(v * 0.70710678118654752f));
            long idx = (long)row * Nd + col;
            if (RES) v += R[idx];
            C[idx] = v;
        }
    }
}

// ---------------- attention scores ----------------
__global__ void scores_kernel(const float* __restrict__ qkv, float* __restrict__ attn)
{
    __shared__ float Qs[32][65];
    __shared__ float Ks[32][65];
    int bh = blockIdx.z;
    int b = bh / NH, hh = bh % NH;
    int n0 = blockIdx.y * 32, m0 = blockIdx.x * 32;
    int t = threadIdx.x;
    #pragma unroll
    for (int i = 0; i < 2; i++) {
        int f = t + i * 256;
        int row = f >> 4;
        int d4 = (f & 15) * 4;
        int nq = n0 + row;
        float4 qv = make_float4(0.f, 0.f, 0.f, 0.f);
        if (nq < NT)
            qv = *(const float4*)(qkv + ((long)(b * NT + nq) * 3 + 0) * DIMV + hh * HD + d4);
        Qs[row][d4] = qv.x; Qs[row][d4 + 1] = qv.y; Qs[row][d4 + 2] = qv.z; Qs[row][d4 + 3] = qv.w;
        int nk = m0 + row;
        float4 kv = make_float4(0.f, 0.f, 0.f, 0.f);
        if (nk < NT)
            kv = *(const float4*)(qkv + ((long)(b * NT + nk) * 3 + 1) * DIMV + hh * HD + d4);
        Ks[row][d4] = kv.x; Ks[row][d4 + 1] = kv.y; Ks[row][d4 + 2] = kv.z; Ks[row][d4 + 3] = kv.w;
    }
    __syncthreads();
    int tx = t & 31, ty = t >> 5;
    float acc[4] = {0.f, 0.f, 0.f, 0.f};
    #pragma unroll 8
    for (int d = 0; d < 64; d++) {
        float kv = Ks[tx][d];
        #pragma unroll
        for (int r = 0; r < 4; r++) acc[r] += Qs[ty * 4 + r][d] * kv;
    }
    #pragma unroll
    for (int r = 0; r < 4; r++) {
        int n = n0 + ty * 4 + r, m = m0 + tx;
        if (n < NT && m < NT)
            attn[(long)bh * NN + (long)n * NT + m] = acc[r] * SCALE_QK;
    }
}

// ---------------- fused attention middle: pre-mix -> softmax -> post-mix ----------------
// One block per (b, n). Smem holds all 12 head-rows of length 197.
__global__ void __launch_bounds__(256) attn_mid_kernel(
    const float* __restrict__ in, const float* __restrict__ pre,
    const float* __restrict__ post, float* __restrict__ out)
{
    __shared__ float rows [NH][NT + 3];
    __shared__ float mixed[NH][NT + 3];
    __shared__ float wpre[NH * NH], wpost[NH * NH];

    int bn = blockIdx.x;
    int b = bn / NT, n = bn % NT;
    int t = threadIdx.x;

    if (t < NH * NH) { wpre[t] = pre[t]; wpost[t] = post[t]; }

    const float* base = in + (long)b * NH * NN + (long)n * NT;
    for (int i = t; i < NH * NT; i += 256) {
        int hh = i / NT, m = i % NT;
        rows[hh][m] = base[(long)hh * NN + m];
    }
    __syncthreads();

    // pre-mix: mixed[g][m] = sum_h rows[h][m] * wpre[h*NH+g]
    if (t < NT) {
        float vin[NH];
        #pragma unroll
        for (int hh = 0; hh < NH; hh++) vin[hh] = rows[hh][t];
        #pragma unroll
        for (int g = 0; g < NH; g++) {
            float s = 0.f;
            #pragma unroll
            for (int hh = 0; hh < NH; hh++) s += vin[hh] * wpre[hh * NH + g];
            mixed[g][t] = s;
        }
    }
    __syncthreads();

    // softmax over m for each row g (warp per row; 8 warps cover 12 rows)
    int warp = t >> 5, lane = t & 31;
    for (int g = warp; g < NH; g += 8) {
        float v[7];
        float mx = -1e30f;
        #pragma unroll
        for (int i = 0; i < 7; i++) {
            int m = lane + i * 32;
            v[i] = (m < NT) ? mixed[g][m] : -1e30f;
            mx = fmaxf(mx, v[i]);
        }
        #pragma unroll
        for (int off = 16; off; off >>= 1) mx = fmaxf(mx, __shfl_xor_sync(0xffffffffu, mx, off));
        float s = 0.f;
        #pragma unroll
        for (int i = 0; i < 7; i++) { v[i] = __expf(v[i] - mx); s += v[i]; }
        #pragma unroll
        for (int off = 16; off; off >>= 1) s += __shfl_xor_sync(0xffffffffu, s, off);
        float inv = 1.0f / s;
        #pragma unroll
        for (int i = 0; i < 7; i++) {
            int m = lane + i * 32;
            if (m < NT) mixed[g][m] = v[i] * inv;
        }
    }
    __syncthreads();

    // post-mix + writeout: out[b,g2,n,m] = sum_g mixed[g][m] * wpost[g*NH+g2]
    if (t < NT) {
        float vm[NH];
        #pragma unroll
        for (int g = 0; g < NH; g++) vm[g] = mixed[g][t];
        float* obase = out + (long)b * NH * NN + (long)n * NT;
        #pragma unroll
        for (int g2 = 0; g2 < NH; g2++) {
            float s = 0.f;
            #pragma unroll
            for (int g = 0; g < NH; g++) s += vm[g] * wpost[g * NH + g2];
            obase[(long)g2 * NN + t] = s;
        }
    }
}

// ---------------- AV ----------------
__global__ void av_kernel(const float* __restrict__ attn, const float* __restrict__ qkv,
                          float* __restrict__ o)
{
    __shared__ float As[32][33];
    __shared__ float Vs[32][65];
    int bh = blockIdx.y;
    int b = bh / NH, hh = bh % NH;
    int n0 = blockIdx.x * 32;
    int t = threadIdx.x;
    int d = t & 63, ng = t >> 6;
    float acc[8] = {};
    for (int m0 = 0; m0 < NT; m0 += 32) {
        {
            int row = t >> 3;
            int c4 = (t & 7) * 4;
            int n = n0 + row;
            #pragma unroll
            for (int j = 0; j < 4; j++) {
                int m = m0 + c4 + j;
                As[row][c4 + j] = (n < NT && m < NT)
                    ? attn[(long)bh * NN + (long)n * NT + m] : 0.f;
            }
        }
        #pragma unroll
        for (int i = 0; i < 2; i++) {
            int f = t + i * 256;
            int row = f >> 4;
            int d4 = (f & 15) * 4;
            int m = m0 + row;
            float4 vv = make_float4(0.f, 0.f, 0.f, 0.f);
            if (m < NT)
                vv = *(const float4*)(qkv + ((long)(b * NT + m) * 3 + 2) * DIMV + hh * HD + d4);
            Vs[row][d4] = vv.x; Vs[row][d4 + 1] = vv.y; Vs[row][d4 + 2] = vv.z; Vs[row][d4 + 3] = vv.w;
        }
        __syncthreads();
        #pragma unroll
        for (int mm = 0; mm < 32; mm++) {
            float vv = Vs[mm][d];
            #pragma unroll
            for (int rr = 0; rr < 8; rr++) acc[rr] += As[ng * 8 + rr][mm] * vv;
        }
        __syncthreads();
    }
    #pragma unroll
    for (int rr = 0; rr < 8; rr++) {
        int n = n0 + ng * 8 + rr;
        if (n < NT) o[(long)(b * NT + n) * DIMV + hh * HD + d] = acc[rr];
    }
}

// ---------------- host launcher ----------------
extern "C" void kernel_launch(void* const* d_in, const int* in_sizes, int n_in,
                              void* d_out, int out_size)
{
    const float* x          = (const float*)d_in[0];
    const float* patch_w    = (const float*)d_in[1];
    const float* patch_b    = (const float*)d_in[2];
    const float* cls_token  = (const float*)d_in[3];
    const float* pos_embed  = (const float*)d_in[4];
    const float* ln1_w      = (const float*)d_in[5];
    const float* ln1_b      = (const float*)d_in[6];
    const float* qkv_w      = (const float*)d_in[7];
    const float* qkv_b      = (const float*)d_in[8];
    const float* pre_w      = (const float*)d_in[9];
    const float* post_w     = (const float*)d_in[10];
    const float* attnproj_w = (const float*)d_in[11];
    const float* attnproj_b = (const float*)d_in[12];
    const float* ln2_w      = (const float*)d_in[13];
    const float* ln2_b      = (const float*)d_in[14];
    const float* fc1_w      = (const float*)d_in[15];
    const float* fc1_b      = (const float*)d_in[16];
    const float* fc2_w      = (const float*)d_in[17];
    const float* fc2_b      = (const float*)d_in[18];
    const float* norm_w     = (const float*)d_in[19];
    const float* norm_b     = (const float*)d_in[20];
    const float* head_w     = (const float*)d_in[21];
    const float* head_b     = (const float*)d_in[22];

    float *p, *pe, *h, *a, *qkv, *attn, *attn2, *o, *ffn, *cls;
    cudaGetSymbolAddress((void**)&p,     g_p);
    cudaGetSymbolAddress((void**)&pe,    g_pe);
    cudaGetSymbolAddress((void**)&h,     g_h);
    cudaGetSymbolAddress((void**)&a,     g_a);
    cudaGetSymbolAddress((void**)&qkv,   g_qkv);
    cudaGetSymbolAddress((void**)&attn,  g_attn);
    cudaGetSymbolAddress((void**)&attn2, g_attn2);
    cudaGetSymbolAddress((void**)&o,     g_o);
    cudaGetSymbolAddress((void**)&ffn,   g_ffn);
    cudaGetSymbolAddress((void**)&cls,   g_cls);

    // patch embedding
    {
        long tot = (long)MPAT * DIMV;
        build_patches_kernel<<<(unsigned)((tot + 255) / 256), 256>>>(x, p);
        gemm_tc<0, 0><<<dim3(6, 49), 256>>>(p, patch_w, patch_b, nullptr, pe, MPAT, DIMV, DIMV);
        long tot2 = (long)MTOK * DIMV;
        assemble_kernel<<<(unsigned)((tot2 + 255) / 256), 256>>>(pe, cls_token, pos_embed, h);
    }

    const unsigned MT = (MTOK + 127) / 128;   // 50

    for (int i = 0; i < 12; i++) {
        ln_kernel<<<MTOK, 256>>>(h, DIMV, ln1_w + i * DIMV, ln1_b + i * DIMV, a);
        gemm_tc<0, 0><<<dim3(18, MT), 256>>>(a, qkv_w + (long)i * DIMV * H3,
                                             qkv_b + i * H3, nullptr, qkv, MTOK, DIMV, H3);
        scores_kernel<<<dim3(7, 7, BB * NH), 256>>>(qkv, attn);
        attn_mid_kernel<<<BB * NT, 256>>>(attn, pre_w + i * NH * NH,
                                          post_w + i * NH * NH, attn2);
        av_kernel<<<dim3(7, BB * NH), 256>>>(attn2, qkv, o);
        gemm_tc<0, 1><<<dim3(6, MT), 256>>>(o, attnproj_w + (long)i * DIMV * DIMV,
                                            attnproj_b + i * DIMV, h, h, MTOK, DIMV, DIMV);
        ln_kernel<<<MTOK, 256>>>(h, DIMV, ln2_w + i * DIMV, ln2_b + i * DIMV, a);
        gemm_tc<1, 0><<<dim3(24, MT), 256>>>(a, fc1_w + (long)i * DIMV * HID,
                                             fc1_b + i * HID, nullptr, ffn, MTOK, DIMV, HID);
        gemm_tc<0, 1><<<dim3(6, MT), 256>>>(ffn, fc2_w + (long)i * HID * DIMV,
                                            fc2_b + i * DIMV, h, h, MTOK, HID, DIMV);
    }

    // final LN on cls rows only, then classifier head (tiny -> SIMT kernel)
    ln_kernel<<<BB, 256>>>(h, (long)NT * DIMV, norm_w, norm_b, cls);
    gemm_kernel<0, 0><<<dim3(16, 1), 256>>>(cls, head_w, head_b, nullptr,
                                            (float*)d_out, BB, DIMV, NC);
}

// round 8
// speedup vs baseline: 2.3913x; 1.2174x over previous
#include <cuda_runtime.h>
#include <math.h>
#include <stdint.h>

// ---------------- model constants ----------------
#define BB    32
#define NPAT  196
#define NT    197
#define DIMV  768
#define H3    2304
#define HID   3072
#define NH    12
#define HD    64
#define NC    1000
#define MTOK  (BB*NT)     // 6304
#define MPAT  (BB*NPAT)   // 6272
#define NN    (NT*NT)     // 38809
#define SCALE_QK 0.125f
#define LNEPS 1e-6f

// ---------------- scratch (device globals; no allocation allowed) ----------------
__device__ float g_p   [(size_t)MPAT*DIMV];
__device__ float g_pe  [(size_t)MPAT*DIMV];
__device__ float g_h   [(size_t)MTOK*DIMV];
__device__ float g_a   [(size_t)MTOK*DIMV];
__device__ float g_qkv [(size_t)MTOK*H3];
__device__ float g_attn[(size_t)BB*NH*NN];
__device__ float g_attn2[(size_t)BB*NH*NN];
__device__ float g_o   [(size_t)MTOK*DIMV];
__device__ float g_ffn [(size_t)MTOK*HID];
__device__ float g_cls [(size_t)BB*DIMV];

// cvt.rna.tf32.f32 requires a .b32 destination register.
__device__ __forceinline__ float to_tf32(float x) {
    uint32_t r;
    asm("cvt.rna.tf32.f32 %0, %1;" : "=r"(r) : "f"(x));
    return __uint_as_float(r);
}
__device__ __forceinline__ float4 to_tf32_4(float4 v) {
    return make_float4(to_tf32(v.x), to_tf32(v.y), to_tf32(v.z), to_tf32(v.w));
}

// ---------------- patch gather ----------------
__global__ void build_patches_kernel(const float* __restrict__ x, float* __restrict__ p)
{
    long idx = (long)blockIdx.x * 256 + threadIdx.x;
    if (idx >= (long)MPAT * DIMV) return;
    int c  = (int)(idx % DIMV);
    long t = idx / DIMV;
    int np = (int)(t % NPAT);
    int b  = (int)(t / NPAT);
    int ch = c >> 8, rem = c & 255, py = rem >> 4, px = rem & 15;
    int gy = np / 14, gx = np % 14;
    p[idx] = x[(((long)b * 3 + ch) * 224 + gy * 16 + py) * 224 + gx * 16 + px];
}

// ---------------- assemble h = concat(cls, patch_out) + pos ----------------
__global__ void assemble_kernel(const float* __restrict__ pe, const float* __restrict__ cls_t,
                                const float* __restrict__ pos, float* __restrict__ h)
{
    long idx = (long)blockIdx.x * 256 + threadIdx.x;
    if (idx >= (long)MTOK * DIMV) return;
    int c  = (int)(idx % DIMV);
    long t = idx / DIMV;
    int n  = (int)(t % NT);
    int b  = (int)(t / NT);
    float v = (n == 0) ? cls_t[c] : pe[((long)b * NPAT + (n - 1)) * DIMV + c];
    h[idx] = v + pos[(long)n * DIMV + c];
}

// ---------------- layernorm ----------------
__global__ void ln_kernel(const float* __restrict__ x, long xstride,
                          const float* __restrict__ w, const float* __restrict__ b,
                          float* __restrict__ out)
{
    int row = blockIdx.x;
    const float* xr = x + (long)row * xstride;
    int t = threadIdx.x;
    float v0 = xr[t], v1 = xr[t + 256], v2 = xr[t + 512];
    float s1 = v0 + v1 + v2;
    float s2 = v0 * v0 + v1 * v1 + v2 * v2;
    #pragma unroll
    for (int off = 16; off; off >>= 1) {
        s1 += __shfl_xor_sync(0xffffffffu, s1, off);
        s2 += __shfl_xor_sync(0xffffffffu, s2, off);
    }
    __shared__ float r1[8], r2[8];
    if ((t & 31) == 0) { r1[t >> 5] = s1; r2[t >> 5] = s2; }
    __syncthreads();
    float tot1 = 0.f, tot2 = 0.f;
    #pragma unroll
    for (int i = 0; i < 8; i++) { tot1 += r1[i]; tot2 += r2[i]; }
    float mean = tot1 * (1.0f / 768.0f);
    float var  = tot2 * (1.0f / 768.0f) - mean * mean;
    float rstd = rsqrtf(var + LNEPS);
    float* orow = out + (long)row * DIMV;
    orow[t]       = (v0 - mean) * rstd * w[t]       + b[t];
    orow[t + 256] = (v1 - mean) * rstd * w[t + 256] + b[t + 256];
    orow[t + 512] = (v2 - mean) * rstd * w[t + 512] + b[t + 512];
}

// ---------------- TF32 tensor-core GEMM, register double-buffered ----------------
// C[M,Nd] = A[M,K] @ W[K,Nd] + bias (+gelu / +residual)
// 128x128x32 block tile, 256 threads = 4(M) x 2(N) warps, warp tile 32x64.
// Global loads of chunk k+1 are issued before the MMAs of chunk k (reg prefetch).
template<int ACT, int RES>
__global__ void __launch_bounds__(256) gemm_tc(
    const float* __restrict__ A, const float* __restrict__ W,
    const float* __restrict__ bias, const float* __restrict__ R,
    float* __restrict__ C, int M, int K, int Nd)
{
    __shared__ __align__(16) float As[128][36];   // row stride 144B (16B mult)
    __shared__ __align__(16) float Bs[32][136];   // row stride 544B (16B mult)

    int tid  = threadIdx.x;
    int warp = tid >> 5, lane = tid & 31;
    int g = lane >> 2, tig = lane & 3;
    int wm = (warp & 3) * 32;
    int wn = (warp >> 2) * 64;
    int m0 = blockIdx.y * 128;
    int n0 = blockIdx.x * 128;

    float c[2][8][4];
    #pragma unroll
    for (int im = 0; im < 2; im++)
        #pragma unroll
        for (int jn = 0; jn < 8; jn++)
            #pragma unroll
            for (int q = 0; q < 4; q++) c[im][jn][q] = 0.f;

    int ar = tid >> 3;              // 0..31
    int ac = (tid & 7) * 4;         // 0..28
    int bk = tid >> 5;              // 0..7
    int bc = (tid & 31) * 4;        // 0..124

    float4 pa[4], pb[4];

    #define LOAD_TILE(k0)                                                        \
        {                                                                        \
            _Pragma("unroll")                                                    \
            for (int i = 0; i < 4; i++) {                                        \
                int row = ar + 32 * i;                                           \
                pa[i] = make_float4(0.f, 0.f, 0.f, 0.f);                         \
                if (m0 + row < M)                                                \
                    pa[i] = *(const float4*)(A + (long)(m0 + row) * K + (k0) + ac); \
            }                                                                    \
            _Pragma("unroll")                                                    \
            for (int i = 0; i < 4; i++) {                                        \
                int kk = bk + 8 * i;                                             \
                pb[i] = *(const float4*)(W + (long)((k0) + kk) * Nd + n0 + bc);  \
            }                                                                    \
        }

    #define STORE_TILE()                                                         \
        {                                                                        \
            _Pragma("unroll")                                                    \
            for (int i = 0; i < 4; i++)                                          \
                *(float4*)&As[ar + 32 * i][ac] = to_tf32_4(pa[i]);               \
            _Pragma("unroll")                                                    \
            for (int i = 0; i < 4; i++)                                          \
                *(float4*)&Bs[bk + 8 * i][bc] = to_tf32_4(pb[i]);                \
        }

    LOAD_TILE(0);
    STORE_TILE();

    for (int k0 = 0; k0 < K; k0 += 32) {
        __syncthreads();
        bool has_next = (k0 + 32) < K;
        if (has_next) LOAD_TILE(k0 + 32);

        #pragma unroll
        for (int ks = 0; ks < 4; ks++) {
            uint32_t a[2][4], b[8][2];
            #pragma unroll
            for (int im = 0; im < 2; im++) {
                int r = wm + im * 16 + g;
                int cc = ks * 8 + tig;
                a[im][0] = __float_as_uint(As[r][cc]);
                a[im][1] = __float_as_uint(As[r + 8][cc]);
                a[im][2] = __float_as_uint(As[r][cc + 4]);
                a[im][3] = __float_as_uint(As[r + 8][cc + 4]);
            }
            #pragma unroll
            for (int jn = 0; jn < 8; jn++) {
                int col = wn + jn * 8 + g;
                b[jn][0] = __float_as_uint(Bs[ks * 8 + tig][col]);
                b[jn][1] = __float_as_uint(Bs[ks * 8 + tig + 4][col]);
            }
            #pragma unroll
            for (int im = 0; im < 2; im++)
                #pragma unroll
                for (int jn = 0; jn < 8; jn++) {
                    asm volatile(
                        "mma.sync.aligned.m16n8k8.row.col.f32.tf32.tf32.f32 "
                        "{%0,%1,%2,%3}, {%4,%5,%6,%7}, {%8,%9}, {%0,%1,%2,%3};"
                        : "+f"(c[im][jn][0]), "+f"(c[im][jn][1]),
                          "+f"(c[im][jn][2]), "+f"(c[im][jn][3])
                        : "r"(a[im][0]), "r"(a[im][1]), "r"(a[im][2]), "r"(a[im][3]),
                          "r"(b[jn][0]), "r"(b[jn][1]));
                }
        }
        __syncthreads();
        if (has_next) STORE_TILE();
    }

    #undef LOAD_TILE
    #undef STORE_TILE

    // epilogue
    #pragma unroll
    for (int im = 0; im < 2; im++) {
        int r0 = m0 + wm + im * 16 + g;
        #pragma unroll
        for (int jn = 0; jn < 8; jn++) {
            int col0 = n0 + wn + jn * 8 + tig * 2;
            #pragma unroll
            for (int q = 0; q < 4; q++) {
                int row = r0 + (q >= 2 ? 8 : 0);
                int col = col0 + (q & 1);
                if (row >= M || col >= Nd) continue;
                float v = c[im][jn][q] + bias[col];
                if (ACT == 1) v = 0.5f * v * (1.0f + erff(v * 0.70710678118654752f));
                long idx = (long)row * Nd + col;
                if (RES) v += R[idx];
                C[idx] = v;
            }
        }
    }
}

// ---------------- fallback SIMT GEMM (head only: M=32) ----------------
template<int ACT, int RES>
__global__ void gemm_kernel(const float* __restrict__ A, const float* __restrict__ W,
                            const float* __restrict__ bias, const float* __restrict__ R,
                            float* __restrict__ C, int M, int K, int Nd)
{
    __shared__ float As[16][64];
    __shared__ float Bs[16][64];
    int tid = threadIdx.x;
    int tx = tid & 15, ty = tid >> 4;
    int m0 = blockIdx.y * 64;
    int n0 = blockIdx.x * 64;
    float acc[4][4] = {};
    int arow = tid >> 2;
    int ak   = (tid & 3) * 4;
    int bk   = tid >> 4;
    int bcol = (tid & 15) * 4;

    for (int k0 = 0; k0 < K; k0 += 16) {
        float4 av = make_float4(0.f, 0.f, 0.f, 0.f);
        if (m0 + arow < M)
            av = *(const float4*)(A + (long)(m0 + arow) * K + k0 + ak);
        As[ak + 0][arow] = av.x; As[ak + 1][arow] = av.y;
        As[ak + 2][arow] = av.z; As[ak + 3][arow] = av.w;

        float4 bv;
        if (n0 + bcol + 3 < Nd) {
            bv = *(const float4*)(W + (long)(k0 + bk) * Nd + n0 + bcol);
        } else {
            const float* wp = W + (long)(k0 + bk) * Nd + n0 + bcol;
            float tmp[4] = {0.f, 0.f, 0.f, 0.f};
            #pragma unroll
            for (int j = 0; j < 4; j++) if (n0 + bcol + j < Nd) tmp[j] = wp[j];
            bv = make_float4(tmp[0], tmp[1], tmp[2], tmp[3]);
        }
        *(float4*)&Bs[bk][bcol] = bv;
        __syncthreads();

        #pragma unroll
        for (int kk = 0; kk < 16; kk++) {
            float4 a = *(const float4*)&As[kk][ty * 4];
            float4 b = *(const float4*)&Bs[kk][tx * 4];
            float ar[4] = {a.x, a.y, a.z, a.w};
            float br[4] = {b.x, b.y, b.z, b.w};
            #pragma unroll
            for (int i = 0; i < 4; i++)
                #pragma unroll
                for (int j = 0; j < 4; j++)
                    acc[i][j] += ar[i] * br[j];
        }
        __syncthreads();
    }

    #pragma unroll
    for (int i = 0; i < 4; i++) {
        int row = m0 + ty * 4 + i;
        if (row >= M) continue;
        #pragma unroll
        for (int j = 0; j < 4; j++) {
            int col = n0 + tx * 4 + j;
            if (col >= Nd) continue;
            float v = acc[i][j] + bias[col];
            if (ACT == 1) v = 0.5f * v * (1.0f + erff(v * 0.70710678118654752f));
            long idx = (long)row * Nd + col;
            if (RES) v += R[idx];
            C[idx] = v;
        }
    }
}

// ---------------- attention scores ----------------
__global__ void scores_kernel(const float* __restrict__ qkv, float* __restrict__ attn)
{
    __shared__ float Qs[32][65];
    __shared__ float Ks[32][65];
    int bh = blockIdx.z;
    int b = bh / NH, hh = bh % NH;
    int n0 = blockIdx.y * 32, m0 = blockIdx.x * 32;
    int t = threadIdx.x;
    #pragma unroll
    for (int i = 0; i < 2; i++) {
        int f = t + i * 256;
        int row = f >> 4;
        int d4 = (f & 15) * 4;
        int nq = n0 + row;
        float4 qv = make_float4(0.f, 0.f, 0.f, 0.f);
        if (nq < NT)
            qv = *(const float4*)(qkv + ((long)(b * NT + nq) * 3 + 0) * DIMV + hh * HD + d4);
        Qs[row][d4] = qv.x; Qs[row][d4 + 1] = qv.y; Qs[row][d4 + 2] = qv.z; Qs[row][d4 + 3] = qv.w;
        int nk = m0 + row;
        float4 kv = make_float4(0.f, 0.f, 0.f, 0.f);
        if (nk < NT)
            kv = *(const float4*)(qkv + ((long)(b * NT + nk) * 3 + 1) * DIMV + hh * HD + d4);
        Ks[row][d4] = kv.x; Ks[row][d4 + 1] = kv.y; Ks[row][d4 + 2] = kv.z; Ks[row][d4 + 3] = kv.w;
    }
    __syncthreads();
    int tx = t & 31, ty = t >> 5;
    float acc[4] = {0.f, 0.f, 0.f, 0.f};
    #pragma unroll 8
    for (int d = 0; d < 64; d++) {
        float kv = Ks[tx][d];
        #pragma unroll
        for (int r = 0; r < 4; r++) acc[r] += Qs[ty * 4 + r][d] * kv;
    }
    #pragma unroll
    for (int r = 0; r < 4; r++) {
        int n = n0 + ty * 4 + r, m = m0 + tx;
        if (n < NT && m < NT)
            attn[(long)bh * NN + (long)n * NT + m] = acc[r] * SCALE_QK;
    }
}

// ---------------- fused attention middle: pre-mix -> softmax -> post-mix ----------------
__global__ void __launch_bounds__(256) attn_mid_kernel(
    const float* __restrict__ in, const float* __restrict__ pre,
    const float* __restrict__ post, float* __restrict__ out)
{
    __shared__ float rows [NH][NT + 3];
    __shared__ float mixed[NH][NT + 3];
    __shared__ float wpre[NH * NH], wpost[NH * NH];

    int bn = blockIdx.x;
    int b = bn / NT, n = bn % NT;
    int t = threadIdx.x;

    if (t < NH * NH) { wpre[t] = pre[t]; wpost[t] = post[t]; }

    const float* base = in + (long)b * NH * NN + (long)n * NT;
    for (int i = t; i < NH * NT; i += 256) {
        int hh = i / NT, m = i % NT;
        rows[hh][m] = base[(long)hh * NN + m];
    }
    __syncthreads();

    if (t < NT) {
        float vin[NH];
        #pragma unroll
        for (int hh = 0; hh < NH; hh++) vin[hh] = rows[hh][t];
        #pragma unroll
        for (int g = 0; g < NH; g++) {
            float s = 0.f;
            #pragma unroll
            for (int hh = 0; hh < NH; hh++) s += vin[hh] * wpre[hh * NH + g];
            mixed[g][t] = s;
        }
    }
    __syncthreads();

    int warp = t >> 5, lane = t & 31;
    for (int g = warp; g < NH; g += 8) {
        float v[7];
        float mx = -1e30f;
        #pragma unroll
        for (int i = 0; i < 7; i++) {
            int m = lane + i * 32;
            v[i] = (m < NT) ? mixed[g][m] : -1e30f;
            mx = fmaxf(mx, v[i]);
        }
        #pragma unroll
        for (int off = 16; off; off >>= 1) mx = fmaxf(mx, __shfl_xor_sync(0xffffffffu, mx, off));
        float s = 0.f;
        #pragma unroll
        for (int i = 0; i < 7; i++) { v[i] = __expf(v[i] - mx); s += v[i]; }
        #pragma unroll
        for (int off = 16; off; off >>= 1) s += __shfl_xor_sync(0xffffffffu, s, off);
        float inv = 1.0f / s;
        #pragma unroll
        for (int i = 0; i < 7; i++) {
            int m = lane + i * 32;
            if (m < NT) mixed[g][m] = v[i] * inv;
        }
    }
    __syncthreads();

    if (t < NT) {
        float vm[NH];
        #pragma unroll
        for (int g = 0; g < NH; g++) vm[g] = mixed[g][t];
        float* obase = out + (long)b * NH * NN + (long)n * NT;
        #pragma unroll
        for (int g2 = 0; g2 < NH; g2++) {
            float s = 0.f;
            #pragma unroll
            for (int g = 0; g < NH; g++) s += vm[g] * wpost[g * NH + g2];
            obase[(long)g2 * NN + t] = s;
        }
    }
}

// ---------------- AV ----------------
__global__ void av_kernel(const float* __restrict__ attn, const float* __restrict__ qkv,
                          float* __restrict__ o)
{
    __shared__ float As[32][33];
    __shared__ float Vs[32][65];
    int bh = blockIdx.y;
    int b = bh / NH, hh = bh % NH;
    int n0 = blockIdx.x * 32;
    int t = threadIdx.x;
    int d = t & 63, ng = t >> 6;
    float acc[8] = {};
    for (int m0 = 0; m0 < NT; m0 += 32) {
        {
            int row = t >> 3;
            int c4 = (t & 7) * 4;
            int n = n0 + row;
            #pragma unroll
            for (int j = 0; j < 4; j++) {
                int m = m0 + c4 + j;
                As[row][c4 + j] = (n < NT && m < NT)
                    ? attn[(long)bh * NN + (long)n * NT + m] : 0.f;
            }
        }
        #pragma unroll
        for (int i = 0; i < 2; i++) {
            int f = t + i * 256;
            int row = f >> 4;
            int d4 = (f & 15) * 4;
            int m = m0 + row;
            float4 vv = make_float4(0.f, 0.f, 0.f, 0.f);
            if (m < NT)
                vv = *(const float4*)(qkv + ((long)(b * NT + m) * 3 + 2) * DIMV + hh * HD + d4);
            Vs[row][d4] = vv.x; Vs[row][d4 + 1] = vv.y; Vs[row][d4 + 2] = vv.z; Vs[row][d4 + 3] = vv.w;
        }
        __syncthreads();
        #pragma unroll
        for (int mm = 0; mm < 32; mm++) {
            float vv = Vs[mm][d];
            #pragma unroll
            for (int rr = 0; rr < 8; rr++) acc[rr] += As[ng * 8 + rr][mm] * vv;
        }
        __syncthreads();
    }
    #pragma unroll
    for (int rr = 0; rr < 8; rr++) {
        int n = n0 + ng * 8 + rr;
        if (n < NT) o[(long)(b * NT + n) * DIMV + hh * HD + d] = acc[rr];
    }
}

// ---------------- host launcher ----------------
extern "C" void kernel_launch(void* const* d_in, const int* in_sizes, int n_in,
                              void* d_out, int out_size)
{
    const float* x          = (const float*)d_in[0];
    const float* patch_w    = (const float*)d_in[1];
    const float* patch_b    = (const float*)d_in[2];
    const float* cls_token  = (const float*)d_in[3];
    const float* pos_embed  = (const float*)d_in[4];
    const float* ln1_w      = (const float*)d_in[5];
    const float* ln1_b      = (const float*)d_in[6];
    const float* qkv_w      = (const float*)d_in[7];
    const float* qkv_b      = (const float*)d_in[8];
    const float* pre_w      = (const float*)d_in[9];
    const float* post_w     = (const float*)d_in[10];
    const float* attnproj_w = (const float*)d_in[11];
    const float* attnproj_b = (const float*)d_in[12];
    const float* ln2_w      = (const float*)d_in[13];
    const float* ln2_b      = (const float*)d_in[14];
    const float* fc1_w      = (const float*)d_in[15];
    const float* fc1_b      = (const float*)d_in[16];
    const float* fc2_w      = (const float*)d_in[17];
    const float* fc2_b      = (const float*)d_in[18];
    const float* norm_w     = (const float*)d_in[19];
    const float* norm_b     = (const float*)d_in[20];
    const float* head_w     = (const float*)d_in[21];
    const float* head_b     = (const float*)d_in[22];

    float *p, *pe, *h, *a, *qkv, *attn, *attn2, *o, *ffn, *cls;
    cudaGetSymbolAddress((void**)&p,     g_p);
    cudaGetSymbolAddress((void**)&pe,    g_pe);
    cudaGetSymbolAddress((void**)&h,     g_h);
    cudaGetSymbolAddress((void**)&a,     g_a);
    cudaGetSymbolAddress((void**)&qkv,   g_qkv);
    cudaGetSymbolAddress((void**)&attn,  g_attn);
    cudaGetSymbolAddress((void**)&attn2, g_attn2);
    cudaGetSymbolAddress((void**)&o,     g_o);
    cudaGetSymbolAddress((void**)&ffn,   g_ffn);
    cudaGetSymbolAddress((void**)&cls,   g_cls);

    // patch embedding
    {
        long tot = (long)MPAT * DIMV;
        build_patches_kernel<<<(unsigned)((tot + 255) / 256), 256>>>(x, p);
        gemm_tc<0, 0><<<dim3(6, 49), 256>>>(p, patch_w, patch_b, nullptr, pe, MPAT, DIMV, DIMV);
        long tot2 = (long)MTOK * DIMV;
        assemble_kernel<<<(unsigned)((tot2 + 255) / 256), 256>>>(pe, cls_token, pos_embed, h);
    }

    const unsigned MT = (MTOK + 127) / 128;   // 50

    for (int i = 0; i < 12; i++) {
        ln_kernel<<<MTOK, 256>>>(h, DIMV, ln1_w + i * DIMV, ln1_b + i * DIMV, a);
        gemm_tc<0, 0><<<dim3(18, MT), 256>>>(a, qkv_w + (long)i * DIMV * H3,
                                             qkv_b + i * H3, nullptr, qkv, MTOK, DIMV, H3);
        scores_kernel<<<dim3(7, 7, BB * NH), 256>>>(qkv, attn);
        attn_mid_kernel<<<BB * NT, 256>>>(attn, pre_w + i * NH * NH,
                                          post_w + i * NH * NH, attn2);
        av_kernel<<<dim3(7, BB * NH), 256>>>(attn2, qkv, o);
        gemm_tc<0, 1><<<dim3(6, MT), 256>>>(o, attnproj_w + (long)i * DIMV * DIMV,
                                            attnproj_b + i * DIMV, h, h, MTOK, DIMV, DIMV);
        ln_kernel<<<MTOK, 256>>>(h, DIMV, ln2_w + i * DIMV, ln2_b + i * DIMV, a);
        gemm_tc<1, 0><<<dim3(24, MT), 256>>>(a, fc1_w + (long)i * DIMV * HID,
                                             fc1_b + i * HID, nullptr, ffn, MTOK, DIMV, HID);
        gemm_tc<0, 1><<<dim3(6, MT), 256>>>(ffn, fc2_w + (long)i * HID * DIMV,
                                            fc2_b + i * DIMV, h, h, MTOK, HID, DIMV);
    }

    // final LN on cls rows only, then classifier head (tiny -> SIMT kernel)
    ln_kernel<<<BB, 256>>>(h, (long)NT * DIMV, norm_w, norm_b, cls);
    gemm_kernel<0, 0><<<dim3(16, 1), 256>>>(cls, head_w, head_b, nullptr,
                                            (float*)d_out, BB, DIMV, NC);
}